// round 10
// baseline (speedup 1.0000x reference)
#include <cuda_runtime.h>
#include <math.h>

#define NSTACK 12
#define ZEROOFF 0.001f
#define EPSV 1e-8f
#define CREC 40      // per-step coef record: a[0:12] c[12:24] q[24:36] pop[36] sq[37] pad->40
#define CS 32        // chunk size (T steps per chunk)
#define NCH 8        // number of chunks (T/CS)

// Fixed shapes (B=32, T=256, V=2048) for scratch sizing.
__device__ float g_interp[32 * 256];
__device__ float g_partd[32 * 4 * 256];          // per (b, blk, t): partial sp.latch_{t-1}
__device__ float g_partn[32 * 4 * 256];          // per (b, blk, t): partial ||latch_{t-1}||^2
__device__ float g_partsp[4];                    // per blk: partial ||sp||^2
__device__ float g_coef[32 * 256 * CREC];        // per (b,t) coefficient record
__device__ float g_achunk[32 * NCH * NSTACK];    // per (b,ch,n): prod of a over chunk
__device__ float g_W[32 * NCH * NSTACK * 2048];  // chunk affine offset (y-space)

__device__ __forceinline__ float dot4(float4 a, float4 b) {
    return a.x * b.x + a.y * b.y + a.z * b.z + a.w * b.w;
}

// ---------------------------------------------------------------------------
// K1: interp[b,t] = cos(latch_enable, x[b,t]).  One WARP per row, MLP=8.
// ---------------------------------------------------------------------------
__global__ void k1_interp(const float* __restrict__ x, const float* __restrict__ le, int V) {
    int row = blockIdx.x * 8 + (threadIdx.x >> 5);
    int lane = threadIdx.x & 31;
    const float4* xp = (const float4*)(x + (size_t)row * V);
    const float4* le4 = (const float4*)le;
    float d = 0.f, n = 0.f, m = 0.f;
    for (int i0 = lane; i0 < V / 4; i0 += 128) {
        float4 xv[4], l[4];
        #pragma unroll
        for (int j = 0; j < 4; j++) { xv[j] = xp[i0 + 32 * j]; l[j] = le4[i0 + 32 * j]; }
        #pragma unroll
        for (int j = 0; j < 4; j++) {
            d += dot4(l[j], xv[j]);
            n += dot4(xv[j], xv[j]);
            m += dot4(l[j], l[j]);
        }
    }
    #pragma unroll
    for (int o = 16; o > 0; o >>= 1) {
        d += __shfl_xor_sync(0xffffffffu, d, o);
        n += __shfl_xor_sync(0xffffffffu, n, o);
        m += __shfl_xor_sync(0xffffffffu, m, o);
    }
    if (lane == 0) {
        float nle = fmaxf(sqrtf(m), EPSV);
        float nx = fmaxf(sqrtf(n), EPSV);
        g_interp[row] = d / (nle * nx);
    }
}

// ---------------------------------------------------------------------------
// K2: latch scan + fused pop partials. grid (4, B), block 128.
// ---------------------------------------------------------------------------
__global__ void k2_latch(const float* __restrict__ x, const float* __restrict__ latch0,
                         const float* __restrict__ sp, float* __restrict__ latches,
                         int T, int V) {
    __shared__ float s_i[256];
    __shared__ float s_wd[256][4];
    __shared__ float s_wn[256][4];
    __shared__ float s_sp[4];
    int b = blockIdx.y;
    int tid = threadIdx.x;
    int lane = tid & 31;
    int w = tid >> 5;
    int v4 = blockIdx.x * blockDim.x + tid;
    int stride4 = V >> 2;

    for (int t = tid; t < T; t += blockDim.x) s_i[t] = g_interp[b * T + t];
    __syncthreads();

    float4 sp4 = ((const float4*)sp)[v4];
    float4 latch = ((const float4*)(latch0 + (size_t)b * V))[v4];
    const float4* xp = (const float4*)(x + (size_t)b * T * V) + v4;
    float4* lp = (float4*)(latches + (size_t)b * T * V) + v4;

    {
        float d = dot4(sp4, latch);
        float n = dot4(latch, latch);
        float m = dot4(sp4, sp4);
        #pragma unroll
        for (int o = 16; o > 0; o >>= 1) {
            d += __shfl_xor_sync(0xffffffffu, d, o);
            n += __shfl_xor_sync(0xffffffffu, n, o);
            m += __shfl_xor_sync(0xffffffffu, m, o);
        }
        if (lane == 0) { s_wd[0][w] = d; s_wn[0][w] = n; s_sp[w] = m; }
    }

    for (int t0 = 0; t0 < T; t0 += 8) {
        float4 xs[8];
        #pragma unroll
        for (int j = 0; j < 8; j++) xs[j] = xp[(size_t)(t0 + j) * stride4];
        float d8[8], n8[8];
        #pragma unroll
        for (int j = 0; j < 8; j++) {
            float i = s_i[t0 + j];
            latch.x = fmaf(i, xs[j].x - latch.x, latch.x);
            latch.y = fmaf(i, xs[j].y - latch.y, latch.y);
            latch.z = fmaf(i, xs[j].z - latch.z, latch.z);
            latch.w = fmaf(i, xs[j].w - latch.w, latch.w);
            lp[(size_t)(t0 + j) * stride4] = latch;
            d8[j] = dot4(sp4, latch);
            n8[j] = dot4(latch, latch);
        }
        #pragma unroll
        for (int o = 16; o > 0; o >>= 1) {
            #pragma unroll
            for (int j = 0; j < 8; j++) {
                d8[j] += __shfl_xor_sync(0xffffffffu, d8[j], o);
                n8[j] += __shfl_xor_sync(0xffffffffu, n8[j], o);
            }
        }
        if (lane == 0) {
            #pragma unroll
            for (int j = 0; j < 8; j++) {
                int t = t0 + j;
                if (t + 1 < T) { s_wd[t + 1][w] = d8[j]; s_wn[t + 1][w] = n8[j]; }
            }
        }
    }
    __syncthreads();
    int pbase = (b * 4 + blockIdx.x) * T;
    for (int t = tid; t < T; t += blockDim.x) {
        g_partd[pbase + t] = s_wd[t][0] + s_wd[t][1] + s_wd[t][2] + s_wd[t][3];
        g_partn[pbase + t] = s_wn[t][0] + s_wn[t][1] + s_wn[t][2] + s_wn[t][3];
    }
    if (b == 0 && tid == 0)
        g_partsp[blockIdx.x] = s_sp[0] + s_sp[1] + s_sp[2] + s_sp[3];
}

// ---------------------------------------------------------------------------
// K4: pops finalize + pointer scan.
// On-chain per step: shfl -> fma mix (pre-scaled push/pop) -> fmax -> ^5.
// Renorm scale lambda (power of 2) computed OFF-chain from redux-max of ph
// and folded into the NEXT step's push/pop. Exact value tracked by rho:
//   v_t = rho_t * u_t;  u_{t+1} = ph^5;  kappa = (rho/lambda)^5;
//   rho_{t+1} = kappa / (kappa*Sum(u_{t+1}) + EPSV).
// All scalings are powers of two => bit-exact vs direct computation.
// ---------------------------------------------------------------------------
__global__ void k4_ptr(const float* __restrict__ sharp_ptr, float* __restrict__ pops, int T) {
    const unsigned FULL = 0xffffffffu;
    __shared__ float s_pop[256];
    int b = blockIdx.x;
    int lane = threadIdx.x;

    float sp2 = g_partsp[0] + g_partsp[1] + g_partsp[2] + g_partsp[3];
    float nsp = fmaxf(sqrtf(sp2), EPSV);
    for (int t = lane; t < T; t += 32) {
        float d = 0.f, n = 0.f;
        #pragma unroll
        for (int blk = 0; blk < 4; blk++) {
            d += g_partd[(b * 4 + blk) * T + t];
            n += g_partn[(b * 4 + blk) * T + t];
        }
        float nl = fmaxf(sqrtf(n), EPSV);
        float c = d / (nsp * nl);
        float p = (c > 0.0f) ? c : expm1f(c);
        s_pop[t] = p;
        pops[b * T + t] = p;
    }
    __syncwarp();

    bool active = lane < NSTACK;
    float sharp = sharp_ptr[0];
    bool fast5 = (sharp == 5.0f);
    float* cbase = g_coef + (size_t)b * T * CREC;
    int src_push = (lane + NSTACK - 1) % NSTACK;
    int src_pop = (lane + 1) % NSTACK;

    float u = (lane == 0) ? 1.0f : 0.0f;   // bounded unnormalized pointer
    float rho = 1.0f;                      // v = rho * u  (exact)
    float lam = 1.0f, invlam = 1.0f;       // power-of-2 renorm for this step
    float Aacc = 1.0f;

    #pragma unroll 4
    for (int t = 0; t < T; t++) {
        float pop = s_pop[t];
        float push = 1.0f - pop;
        float pushs = push * lam;
        float popsc = pop * lam;
        // ---- critical chain ----
        float up = __shfl_sync(FULL, u, src_push);
        float upop = __shfl_sync(FULL, u, src_pop);
        float mh = fmaf(pushs, up, popsc * upop);
        float ph = active ? fmaxf(mh, 0.0f) : 0.0f;
        float u_next;
        if (fast5) {
            float p2 = ph * ph;
            u_next = (p2 * p2) * ph;
        } else {
            u_next = (ph > 0.f) ? powf(ph, sharp) : 0.f;
        }
        // ---- off-chain: next lambda from max(ph) ----
        unsigned pb = __float_as_uint(ph);
        unsigned Mb;
        asm("redux.sync.max.u32 %0, %1, 0xffffffff;" : "=r"(Mb) : "r"(pb));
        int ep = (int)(Mb >> 23) - 127;
        int lexp = 127 - 5 * ep;
        lexp = lexp < 1 ? 1 : (lexp > 253 ? 253 : lexp);
        float lam_next = __uint_as_float((unsigned)lexp << 23);
        float invlam_next = __uint_as_float((unsigned)(254 - lexp) << 23);
        // ---- off-chain: exact scale rho ----
        float S = u_next;
        #pragma unroll
        for (int o = 8; o > 0; o >>= 1) S += __shfl_xor_sync(FULL, S, o);
        float rg = rho * invlam;   // (rho / lam): lam is the scale used THIS step
        float kap;
        if (fast5) {
            float r2 = rg * rg;
            kap = (r2 * r2) * rg;
        } else {
            kap = powf(rg, sharp);
        }
        float rho_next = __fdividef(kap, fmaf(kap, S, EPSV));
        // ---- records for step t (from v_t = rho*u, v_{t+1} = rho_next*u_next) ----
        float vpush = rho * up;
        float vcur = rho * u;
        float a = push * (1.0f - vpush) + pop * (1.0f - vcur);
        float c = push * vpush;
        float q = rho_next * u_next;
        float* cf = cbase + (size_t)t * CREC;
        if (active) {
            cf[lane] = a;
            cf[12 + lane] = c;
            cf[24 + lane] = q;
        }
        if (lane == 0) {
            cf[36] = pop;
            cf[37] = rho_next * S;   // sum of q over the 12 slots
        }
        Aacc *= a;
        if ((t & (CS - 1)) == CS - 1) {
            if (active) g_achunk[(b * NCH + (t >> 5)) * NSTACK + lane] = Aacc;
            Aacc = 1.0f;
        }
        u = u_next;
        rho = rho_next;
        lam = lam_next;
        invlam = invlam_next;
    }
}

// ---------------------------------------------------------------------------
// K6 (pass 1): replay each chunk in y-space from y=0 -> chunk offset W.
// y_next = a*y + c*(x - ZEROOFF).  grid (4, NCH-1, B), block 256.
// ---------------------------------------------------------------------------
__global__ void __launch_bounds__(256, 4)
k6_pass1(const float* __restrict__ x, int T, int V) {
    __shared__ __align__(16) float s_c[CS * CREC];
    int b = blockIdx.z, ch = blockIdx.y;
    int t0 = ch * CS;
    const float4* cg = (const float4*)(g_coef + ((size_t)b * T + t0) * CREC);
    float4* cs4 = (float4*)s_c;
    for (int i = threadIdx.x; i < CS * (CREC / 4); i += blockDim.x) cs4[i] = cg[i];
    __syncthreads();

    int col = blockIdx.x * blockDim.x + threadIdx.x;
    int s2 = V >> 1;
    const float2* xp = (const float2*)(x + (size_t)b * T * V) + (size_t)t0 * s2 + col;

    float yx[NSTACK], yy[NSTACK];
    #pragma unroll
    for (int n = 0; n < NSTACK; n++) { yx[n] = 0.f; yy[n] = 0.f; }

    float2 xbuf[4];
    #pragma unroll
    for (int j = 0; j < 4; j++) xbuf[j] = xp[(size_t)j * s2];

    for (int tt = 0; tt < CS; tt += 4) {
        #pragma unroll
        for (int j = 0; j < 4; j++) {
            int t = tt + j;
            float2 xv = xbuf[j];
            int tpre = (t + 4 < CS) ? t + 4 : CS - 1;
            xbuf[j] = xp[(size_t)tpre * s2];
            float xzx = xv.x - ZEROOFF;
            float xzy = xv.y - ZEROOFF;
            const float4* cf4 = (const float4*)(s_c + t * CREC);
            #pragma unroll
            for (int g = 0; g < 3; g++) {
                float a4[4], c4[4];
                *(float4*)a4 = cf4[g];
                *(float4*)c4 = cf4[3 + g];
                #pragma unroll
                for (int k = 0; k < 4; k++) {
                    int n = 4 * g + k;
                    yx[n] = fmaf(a4[k], yx[n], c4[k] * xzx);
                    yy[n] = fmaf(a4[k], yy[n], c4[k] * xzy);
                }
            }
        }
    }
    float2* Wp = (float2*)g_W + ((size_t)(b * NCH + ch) * NSTACK) * s2 + col;
    #pragma unroll
    for (int n = 0; n < NSTACK; n++) {
        float2 w2; w2.x = yx[n]; w2.y = yy[n];
        Wp[(size_t)n * s2] = w2;
    }
}

// ---------------------------------------------------------------------------
// K8 (pass 2, fused combine): start state from W/A fold (y-space, init 0),
// then replay writing outs/tops.  top = sum(q*y) + ZEROOFF*sq.
// grid (4, NCH, B), block 256.
// ---------------------------------------------------------------------------
__global__ void __launch_bounds__(256, 4)
k8_pass2(const float* __restrict__ x, float* __restrict__ outs,
         float* __restrict__ tops, int T, int V) {
    __shared__ __align__(16) float s_c[CS * CREC];
    __shared__ float sA[NCH - 1][NSTACK];
    int b = blockIdx.z, ch = blockIdx.y;
    int t0 = ch * CS;
    const float4* cg = (const float4*)(g_coef + ((size_t)b * T + t0) * CREC);
    float4* cs4 = (float4*)s_c;
    for (int i = threadIdx.x; i < CS * (CREC / 4); i += blockDim.x) cs4[i] = cg[i];
    if (threadIdx.x < (NCH - 1) * NSTACK)
        sA[threadIdx.x / NSTACK][threadIdx.x % NSTACK] =
            g_achunk[b * NCH * NSTACK + threadIdx.x];
    __syncthreads();

    int col = blockIdx.x * blockDim.x + threadIdx.x;
    int s2 = V >> 1;
    const float2* xp = (const float2*)(x + (size_t)b * T * V) + (size_t)t0 * s2 + col;
    float2* op = (float2*)(outs + (size_t)b * T * V) + (size_t)t0 * s2 + col;
    float2* tp = (float2*)(tops + (size_t)b * T * V) + (size_t)t0 * s2 + col;

    float yx[NSTACK], yy[NSTACK];
    #pragma unroll
    for (int n = 0; n < NSTACK; n++) { yx[n] = 0.f; yy[n] = 0.f; }
    for (int j = 0; j < ch; j++) {
        const float2* Wp = (const float2*)g_W + ((size_t)(b * NCH + j) * NSTACK) * s2 + col;
        float2 w[NSTACK];
        #pragma unroll
        for (int n = 0; n < NSTACK; n++) w[n] = Wp[(size_t)n * s2];
        #pragma unroll
        for (int n = 0; n < NSTACK; n++) {
            float A = sA[j][n];
            yx[n] = fmaf(A, yx[n], w[n].x);
            yy[n] = fmaf(A, yy[n], w[n].y);
        }
    }

    float2 xbuf[4];
    #pragma unroll
    for (int j = 0; j < 4; j++) xbuf[j] = xp[(size_t)j * s2];

    for (int tt = 0; tt < CS; tt += 4) {
        #pragma unroll
        for (int j = 0; j < 4; j++) {
            int t = tt + j;
            float2 xv = xbuf[j];
            int tpre = (t + 4 < CS) ? t + 4 : CS - 1;
            xbuf[j] = xp[(size_t)tpre * s2];
            float xzx = xv.x - ZEROOFF;
            float xzy = xv.y - ZEROOFF;
            const float4* cf4 = (const float4*)(s_c + t * CREC);
            float topx = 0.f, topy = 0.f;
            #pragma unroll
            for (int g = 0; g < 3; g++) {
                float a4[4], c4[4], q4[4];
                *(float4*)a4 = cf4[g];
                *(float4*)c4 = cf4[3 + g];
                *(float4*)q4 = cf4[6 + g];
                #pragma unroll
                for (int k = 0; k < 4; k++) {
                    int n = 4 * g + k;
                    yx[n] = fmaf(a4[k], yx[n], c4[k] * xzx);
                    yy[n] = fmaf(a4[k], yy[n], c4[k] * xzy);
                    topx = fmaf(yx[n], q4[k], topx);
                    topy = fmaf(yy[n], q4[k], topy);
                }
            }
            float pop = s_c[t * CREC + 36];
            float sq = s_c[t * CREC + 37];
            topx = fmaf(ZEROOFF, sq, topx);
            topy = fmaf(ZEROOFF, sq, topy);
            float2 o2; o2.x = pop * topx; o2.y = pop * topy;
            float2 t2; t2.x = topx; t2.y = topy;
            op[(size_t)t * s2] = o2;
            tp[(size_t)t * s2] = t2;
        }
    }
}

// ---------------------------------------------------------------------------
// Launch (5 kernels). Output layout: [outs BTV][latches BTV][pops BT][tops BTV]
// ---------------------------------------------------------------------------
extern "C" void kernel_launch(void* const* d_in, const int* in_sizes, int n_in,
                              void* d_out, int out_size) {
    const float* x = (const float*)d_in[0];
    const float* sp = (const float*)d_in[1];
    const float* shp = (const float*)d_in[2];
    const float* le = (const float*)d_in[3];
    const float* l0 = (const float*)d_in[4];

    int V = in_sizes[1];
    int B = in_sizes[4] / V;
    int T = in_sizes[0] / in_sizes[4];

    float* out = (float*)d_out;
    size_t btv = (size_t)B * T * V;
    float* outs = out;
    float* latches = out + btv;
    float* pops = out + 2 * btv;
    float* tops = out + 2 * btv + (size_t)B * T;

    k1_interp<<<B * T / 8, 256>>>(x, le, V);
    dim3 g2(4, B);
    k2_latch<<<g2, 128>>>(x, l0, sp, latches, T, V);
    k4_ptr<<<B, 32>>>(shp, pops, T);
    dim3 g6(V / 512, NCH - 1, B);
    k6_pass1<<<g6, 256>>>(x, T, V);
    dim3 g8(V / 512, NCH, B);
    k8_pass2<<<g8, 256>>>(x, outs, tops, T, V);
}

// round 11
// speedup vs baseline: 1.1012x; 1.1012x over previous
#include <cuda_runtime.h>
#include <math.h>

#define NSTACK 12
#define ZEROOFF 0.001f
#define EPSV 1e-8f
#define CREC 40      // per-step coef record: a[0:12] c[12:24] q[24:36] pop[36] sq[37] pad->40
#define CS 32        // chunk size (T steps per chunk)
#define NCH 8        // number of chunks (T/CS)
#define KB2 8        // k2 blocks per batch

// Fixed shapes (B=32, T=256, V=2048) for scratch sizing.
__device__ float g_interp[32 * 256];
__device__ float g_partd[32 * KB2 * 256];        // per (b, blk, t): partial sp.latch_{t-1}
__device__ float g_partn[32 * KB2 * 256];        // per (b, blk, t): partial ||latch_{t-1}||^2
__device__ float g_partsp[KB2];                  // per blk: partial ||sp||^2
__device__ float g_coef[32 * 256 * CREC];        // per (b,t) coefficient record
__device__ float g_achunk[32 * NCH * NSTACK];    // per (b,ch,n): prod of a over chunk
__device__ float g_W[32 * NCH * NSTACK * 2048];  // chunk affine offset (y-space)

__device__ __forceinline__ float dot4(float4 a, float4 b) {
    return a.x * b.x + a.y * b.y + a.z * b.z + a.w * b.w;
}

// ---------------------------------------------------------------------------
// K1: interp[b,t] = cos(latch_enable, x[b,t]).  One WARP per row, MLP=8.
// ---------------------------------------------------------------------------
__global__ void k1_interp(const float* __restrict__ x, const float* __restrict__ le, int V) {
    int row = blockIdx.x * 8 + (threadIdx.x >> 5);
    int lane = threadIdx.x & 31;
    const float4* xp = (const float4*)(x + (size_t)row * V);
    const float4* le4 = (const float4*)le;
    float d = 0.f, n = 0.f, m = 0.f;
    for (int i0 = lane; i0 < V / 4; i0 += 128) {
        float4 xv[4], l[4];
        #pragma unroll
        for (int j = 0; j < 4; j++) { xv[j] = xp[i0 + 32 * j]; l[j] = le4[i0 + 32 * j]; }
        #pragma unroll
        for (int j = 0; j < 4; j++) {
            d += dot4(l[j], xv[j]);
            n += dot4(xv[j], xv[j]);
            m += dot4(l[j], l[j]);
        }
    }
    #pragma unroll
    for (int o = 16; o > 0; o >>= 1) {
        d += __shfl_xor_sync(0xffffffffu, d, o);
        n += __shfl_xor_sync(0xffffffffu, n, o);
        m += __shfl_xor_sync(0xffffffffu, m, o);
    }
    if (lane == 0) {
        float nle = fmaxf(sqrtf(m), EPSV);
        float nx = fmaxf(sqrtf(n), EPSV);
        g_interp[row] = d / (nle * nx);
    }
}

// ---------------------------------------------------------------------------
// K2: latch scan + fused pop partials. grid (KB2, B), block 128, float2/thread.
// ---------------------------------------------------------------------------
__global__ void k2_latch(const float* __restrict__ x, const float* __restrict__ latch0,
                         const float* __restrict__ sp, float* __restrict__ latches,
                         int T, int V) {
    __shared__ float s_i[256];
    __shared__ float s_wd[256][4];
    __shared__ float s_wn[256][4];
    __shared__ float s_sp[4];
    int b = blockIdx.y;
    int tid = threadIdx.x;
    int lane = tid & 31;
    int w = tid >> 5;
    int v2 = blockIdx.x * blockDim.x + tid;    // float2 column, 0..1023
    int stride2 = V >> 1;                       // 1024

    for (int t = tid; t < T; t += blockDim.x) s_i[t] = g_interp[b * T + t];
    __syncthreads();

    float2 sp2 = ((const float2*)sp)[v2];
    float2 latch = ((const float2*)(latch0 + (size_t)b * V))[v2];
    const float2* xp = (const float2*)(x + (size_t)b * T * V) + v2;
    float2* lp = (float2*)(latches + (size_t)b * T * V) + v2;

    {
        float d = sp2.x * latch.x + sp2.y * latch.y;
        float n = latch.x * latch.x + latch.y * latch.y;
        float m = sp2.x * sp2.x + sp2.y * sp2.y;
        #pragma unroll
        for (int o = 16; o > 0; o >>= 1) {
            d += __shfl_xor_sync(0xffffffffu, d, o);
            n += __shfl_xor_sync(0xffffffffu, n, o);
            m += __shfl_xor_sync(0xffffffffu, m, o);
        }
        if (lane == 0) { s_wd[0][w] = d; s_wn[0][w] = n; s_sp[w] = m; }
    }

    for (int t0 = 0; t0 < T; t0 += 8) {
        float2 xs[8];
        #pragma unroll
        for (int j = 0; j < 8; j++) xs[j] = xp[(size_t)(t0 + j) * stride2];
        float d8[8], n8[8];
        #pragma unroll
        for (int j = 0; j < 8; j++) {
            float i = s_i[t0 + j];
            latch.x = fmaf(i, xs[j].x - latch.x, latch.x);
            latch.y = fmaf(i, xs[j].y - latch.y, latch.y);
            lp[(size_t)(t0 + j) * stride2] = latch;
            d8[j] = sp2.x * latch.x + sp2.y * latch.y;
            n8[j] = latch.x * latch.x + latch.y * latch.y;
        }
        #pragma unroll
        for (int o = 16; o > 0; o >>= 1) {
            #pragma unroll
            for (int j = 0; j < 8; j++) {
                d8[j] += __shfl_xor_sync(0xffffffffu, d8[j], o);
                n8[j] += __shfl_xor_sync(0xffffffffu, n8[j], o);
            }
        }
        if (lane == 0) {
            #pragma unroll
            for (int j = 0; j < 8; j++) {
                int t = t0 + j;
                if (t + 1 < T) { s_wd[t + 1][w] = d8[j]; s_wn[t + 1][w] = n8[j]; }
            }
        }
    }
    __syncthreads();
    int pbase = (b * KB2 + blockIdx.x) * T;
    for (int t = tid; t < T; t += blockDim.x) {
        g_partd[pbase + t] = s_wd[t][0] + s_wd[t][1] + s_wd[t][2] + s_wd[t][3];
        g_partn[pbase + t] = s_wn[t][0] + s_wn[t][1] + s_wn[t][2] + s_wn[t][3];
    }
    if (b == 0 && tid == 0)
        g_partsp[blockIdx.x] = s_sp[0] + s_sp[1] + s_sp[2] + s_sp[3];
}

// ---------------------------------------------------------------------------
// K4: pops finalize + pointer scan (unnormalized chain, exact rho off-chain).
// ---------------------------------------------------------------------------
__global__ void k4_ptr(const float* __restrict__ sharp_ptr, float* __restrict__ pops, int T) {
    const unsigned FULL = 0xffffffffu;
    __shared__ float s_pop[256];
    int b = blockIdx.x;
    int lane = threadIdx.x;

    float sp2 = 0.f;
    #pragma unroll
    for (int blk = 0; blk < KB2; blk++) sp2 += g_partsp[blk];
    float nsp = fmaxf(sqrtf(sp2), EPSV);
    for (int t = lane; t < T; t += 32) {
        float d = 0.f, n = 0.f;
        #pragma unroll
        for (int blk = 0; blk < KB2; blk++) {
            d += g_partd[(b * KB2 + blk) * T + t];
            n += g_partn[(b * KB2 + blk) * T + t];
        }
        float nl = fmaxf(sqrtf(n), EPSV);
        float c = d / (nsp * nl);
        float p = (c > 0.0f) ? c : expm1f(c);
        s_pop[t] = p;
        pops[b * T + t] = p;
    }
    __syncwarp();

    bool active = lane < NSTACK;
    float sharp = sharp_ptr[0];
    bool fast5 = (sharp == 5.0f);
    float* cbase = g_coef + (size_t)b * T * CREC;
    int src_push = (lane + NSTACK - 1) % NSTACK;
    int src_pop = (lane + 1) % NSTACK;

    float u = (lane == 0) ? 1.0f : 0.0f;
    float rho = 1.0f;
    float lam = 1.0f, invlam = 1.0f;
    float Aacc = 1.0f;

    #pragma unroll 4
    for (int t = 0; t < T; t++) {
        float pop = s_pop[t];
        float push = 1.0f - pop;
        float pushs = push * lam;
        float popsc = pop * lam;
        // ---- critical chain ----
        float up = __shfl_sync(FULL, u, src_push);
        float upop = __shfl_sync(FULL, u, src_pop);
        float mh = fmaf(pushs, up, popsc * upop);
        float ph = active ? fmaxf(mh, 0.0f) : 0.0f;
        float u_next;
        if (fast5) {
            float p2 = ph * ph;
            u_next = (p2 * p2) * ph;
        } else {
            u_next = (ph > 0.f) ? powf(ph, sharp) : 0.f;
        }
        // ---- off-chain: next lambda from max(ph) ----
        unsigned pb = __float_as_uint(ph);
        unsigned Mb;
        asm("redux.sync.max.u32 %0, %1, 0xffffffff;" : "=r"(Mb) : "r"(pb));
        int ep = (int)(Mb >> 23) - 127;
        int lexp = 127 - 5 * ep;
        lexp = lexp < 1 ? 1 : (lexp > 253 ? 253 : lexp);
        float lam_next = __uint_as_float((unsigned)lexp << 23);
        float invlam_next = __uint_as_float((unsigned)(254 - lexp) << 23);
        // ---- off-chain: exact scale rho ----
        float S = u_next;
        #pragma unroll
        for (int o = 8; o > 0; o >>= 1) S += __shfl_xor_sync(FULL, S, o);
        float rg = rho * invlam;
        float kap;
        if (fast5) {
            float r2 = rg * rg;
            kap = (r2 * r2) * rg;
        } else {
            kap = powf(rg, sharp);
        }
        float rho_next = __fdividef(kap, fmaf(kap, S, EPSV));
        // ---- records ----
        float vpush = rho * up;
        float vcur = rho * u;
        float a = push * (1.0f - vpush) + pop * (1.0f - vcur);
        float c = push * vpush;
        float q = rho_next * u_next;
        float* cf = cbase + (size_t)t * CREC;
        if (active) {
            cf[lane] = a;
            cf[12 + lane] = c;
            cf[24 + lane] = q;
        }
        if (lane == 0) {
            cf[36] = pop;
            cf[37] = rho_next * S;   // sum of q
        }
        Aacc *= a;
        if ((t & (CS - 1)) == CS - 1) {
            if (active) g_achunk[(b * NCH + (t >> 5)) * NSTACK + lane] = Aacc;
            Aacc = 1.0f;
        }
        u = u_next;
        rho = rho_next;
        lam = lam_next;
        invlam = invlam_next;
    }
}

// ---------------------------------------------------------------------------
// K6 (pass 1): replay chunk in y-space from y=0 -> W. grid (4, NCH-1, B).
// ---------------------------------------------------------------------------
__global__ void __launch_bounds__(256, 4)
k6_pass1(const float* __restrict__ x, int T, int V) {
    __shared__ __align__(16) float s_c[CS * CREC];
    int b = blockIdx.z, ch = blockIdx.y;
    int t0 = ch * CS;
    const float4* cg = (const float4*)(g_coef + ((size_t)b * T + t0) * CREC);
    float4* cs4 = (float4*)s_c;
    for (int i = threadIdx.x; i < CS * (CREC / 4); i += blockDim.x) cs4[i] = cg[i];
    __syncthreads();

    int col = blockIdx.x * blockDim.x + threadIdx.x;
    int s2 = V >> 1;
    const float2* xp = (const float2*)(x + (size_t)b * T * V) + (size_t)t0 * s2 + col;

    float yx[NSTACK], yy[NSTACK];
    #pragma unroll
    for (int n = 0; n < NSTACK; n++) { yx[n] = 0.f; yy[n] = 0.f; }

    float2 xbuf[4];
    #pragma unroll
    for (int j = 0; j < 4; j++) xbuf[j] = xp[(size_t)j * s2];

    for (int tt = 0; tt < CS; tt += 4) {
        #pragma unroll
        for (int j = 0; j < 4; j++) {
            int t = tt + j;
            float2 xv = xbuf[j];
            int tpre = (t + 4 < CS) ? t + 4 : CS - 1;
            xbuf[j] = xp[(size_t)tpre * s2];
            float xzx = xv.x - ZEROOFF;
            float xzy = xv.y - ZEROOFF;
            const float4* cf4 = (const float4*)(s_c + t * CREC);
            #pragma unroll
            for (int g = 0; g < 3; g++) {
                float a4[4], c4[4];
                *(float4*)a4 = cf4[g];
                *(float4*)c4 = cf4[3 + g];
                #pragma unroll
                for (int k = 0; k < 4; k++) {
                    int n = 4 * g + k;
                    yx[n] = fmaf(a4[k], yx[n], c4[k] * xzx);
                    yy[n] = fmaf(a4[k], yy[n], c4[k] * xzy);
                }
            }
        }
    }
    float2* Wp = (float2*)g_W + ((size_t)(b * NCH + ch) * NSTACK) * s2 + col;
    #pragma unroll
    for (int n = 0; n < NSTACK; n++) {
        float2 w2; w2.x = yx[n]; w2.y = yy[n];
        Wp[(size_t)n * s2] = w2;
    }
}

// ---------------------------------------------------------------------------
// K8 (pass 2, fused combine): start state from W/A fold, replay, write outs/tops.
// grid (4, NCH, B), block 256.
// ---------------------------------------------------------------------------
__global__ void __launch_bounds__(256, 4)
k8_pass2(const float* __restrict__ x, float* __restrict__ outs,
         float* __restrict__ tops, int T, int V) {
    __shared__ __align__(16) float s_c[CS * CREC];
    __shared__ float sA[NCH - 1][NSTACK];
    int b = blockIdx.z, ch = blockIdx.y;
    int t0 = ch * CS;
    const float4* cg = (const float4*)(g_coef + ((size_t)b * T + t0) * CREC);
    float4* cs4 = (float4*)s_c;
    for (int i = threadIdx.x; i < CS * (CREC / 4); i += blockDim.x) cs4[i] = cg[i];
    if (threadIdx.x < (NCH - 1) * NSTACK)
        sA[threadIdx.x / NSTACK][threadIdx.x % NSTACK] =
            g_achunk[b * NCH * NSTACK + threadIdx.x];
    __syncthreads();

    int col = blockIdx.x * blockDim.x + threadIdx.x;
    int s2 = V >> 1;
    const float2* xp = (const float2*)(x + (size_t)b * T * V) + (size_t)t0 * s2 + col;
    float2* op = (float2*)(outs + (size_t)b * T * V) + (size_t)t0 * s2 + col;
    float2* tp = (float2*)(tops + (size_t)b * T * V) + (size_t)t0 * s2 + col;

    float yx[NSTACK], yy[NSTACK];
    #pragma unroll
    for (int n = 0; n < NSTACK; n++) { yx[n] = 0.f; yy[n] = 0.f; }
    for (int j = 0; j < ch; j++) {
        const float2* Wp = (const float2*)g_W + ((size_t)(b * NCH + j) * NSTACK) * s2 + col;
        float2 w[NSTACK];
        #pragma unroll
        for (int n = 0; n < NSTACK; n++) w[n] = Wp[(size_t)n * s2];
        #pragma unroll
        for (int n = 0; n < NSTACK; n++) {
            float A = sA[j][n];
            yx[n] = fmaf(A, yx[n], w[n].x);
            yy[n] = fmaf(A, yy[n], w[n].y);
        }
    }

    float2 xbuf[4];
    #pragma unroll
    for (int j = 0; j < 4; j++) xbuf[j] = xp[(size_t)j * s2];

    for (int tt = 0; tt < CS; tt += 4) {
        #pragma unroll
        for (int j = 0; j < 4; j++) {
            int t = tt + j;
            float2 xv = xbuf[j];
            int tpre = (t + 4 < CS) ? t + 4 : CS - 1;
            xbuf[j] = xp[(size_t)tpre * s2];
            float xzx = xv.x - ZEROOFF;
            float xzy = xv.y - ZEROOFF;
            const float4* cf4 = (const float4*)(s_c + t * CREC);
            float topx = 0.f, topy = 0.f;
            #pragma unroll
            for (int g = 0; g < 3; g++) {
                float a4[4], c4[4], q4[4];
                *(float4*)a4 = cf4[g];
                *(float4*)c4 = cf4[3 + g];
                *(float4*)q4 = cf4[6 + g];
                #pragma unroll
                for (int k = 0; k < 4; k++) {
                    int n = 4 * g + k;
                    yx[n] = fmaf(a4[k], yx[n], c4[k] * xzx);
                    yy[n] = fmaf(a4[k], yy[n], c4[k] * xzy);
                    topx = fmaf(yx[n], q4[k], topx);
                    topy = fmaf(yy[n], q4[k], topy);
                }
            }
            float meta[4];
            *(float4*)meta = cf4[9];   // pop, sq, pad, pad — one LDS.128
            float pop = meta[0];
            float sq = meta[1];
            topx = fmaf(ZEROOFF, sq, topx);
            topy = fmaf(ZEROOFF, sq, topy);
            float2 o2; o2.x = pop * topx; o2.y = pop * topy;
            float2 t2; t2.x = topx; t2.y = topy;
            op[(size_t)t * s2] = o2;
            tp[(size_t)t * s2] = t2;
        }
    }
}

// ---------------------------------------------------------------------------
// Launch (5 kernels). Output layout: [outs BTV][latches BTV][pops BT][tops BTV]
// ---------------------------------------------------------------------------
extern "C" void kernel_launch(void* const* d_in, const int* in_sizes, int n_in,
                              void* d_out, int out_size) {
    const float* x = (const float*)d_in[0];
    const float* sp = (const float*)d_in[1];
    const float* shp = (const float*)d_in[2];
    const float* le = (const float*)d_in[3];
    const float* l0 = (const float*)d_in[4];

    int V = in_sizes[1];
    int B = in_sizes[4] / V;
    int T = in_sizes[0] / in_sizes[4];

    float* out = (float*)d_out;
    size_t btv = (size_t)B * T * V;
    float* outs = out;
    float* latches = out + btv;
    float* pops = out + 2 * btv;
    float* tops = out + 2 * btv + (size_t)B * T;

    k1_interp<<<B * T / 8, 256>>>(x, le, V);
    dim3 g2(KB2, B);
    k2_latch<<<g2, 128>>>(x, l0, sp, latches, T, V);
    k4_ptr<<<B, 32>>>(shp, pops, T);
    dim3 g6(V / 512, NCH - 1, B);
    k6_pass1<<<g6, 256>>>(x, T, V);
    dim3 g8(V / 512, NCH, B);
    k8_pass2<<<g8, 256>>>(x, outs, tops, T, V);
}

// round 12
// speedup vs baseline: 1.1028x; 1.0014x over previous
#include <cuda_runtime.h>
#include <math.h>

#define NSTACK 12
#define ZEROOFF 0.001f
#define EPSV 1e-8f
#define CREC 40      // a[0:12] c[12:24] q[24:36] pop[36] sq[37] pad->40
#define CS 32        // chunk size
#define NCH 8        // chunks (T/CS)
#define KB2 8        // k2 blocks per batch

// Fixed shapes (B=32, T=256, V=2048).
__device__ float g_interp[32 * 256];
__device__ float g_partd[32 * KB2 * 256];
__device__ float g_partn[32 * KB2 * 256];
__device__ float g_partsp[KB2];
__device__ float g_coef[32 * 256 * CREC];
__device__ __align__(16) float g_achunk[32 * NCH * NSTACK];
__device__ __align__(16) float g_W[32 * NCH * 2048 * NSTACK];  // [b][ch][col][n]

typedef unsigned long long ull;

__device__ __forceinline__ ull pack2(float lo, float hi) {
    ull r;
    asm("mov.b64 %0, {%1, %2};" : "=l"(r) : "f"(lo), "f"(hi));
    return r;
}
__device__ __forceinline__ void unpack2(ull v, float& lo, float& hi) {
    asm("mov.b64 {%0, %1}, %2;" : "=f"(lo), "=f"(hi) : "l"(v));
}
__device__ __forceinline__ ull fma2(ull a, ull b, ull c) {
    ull d;
    asm("fma.rn.f32x2 %0, %1, %2, %3;" : "=l"(d) : "l"(a), "l"(b), "l"(c));
    return d;
}
__device__ __forceinline__ ull mul2(ull a, ull b) {
    ull d;
    asm("mul.rn.f32x2 %0, %1, %2;" : "=l"(d) : "l"(a), "l"(b));
    return d;
}

// ---------------------------------------------------------------------------
// KZ: splitter so ncu's captured (4th) launch is k4.
// ---------------------------------------------------------------------------
__global__ void kz_split() {}

// ---------------------------------------------------------------------------
// K1: interp[b,t] = cos(latch_enable, x[b,t]).  One WARP per row, MLP=8.
// ---------------------------------------------------------------------------
__global__ void k1_interp(const float* __restrict__ x, const float* __restrict__ le, int V) {
    int row = blockIdx.x * 8 + (threadIdx.x >> 5);
    int lane = threadIdx.x & 31;
    const float4* xp = (const float4*)(x + (size_t)row * V);
    const float4* le4 = (const float4*)le;
    float d = 0.f, n = 0.f, m = 0.f;
    for (int i0 = lane; i0 < V / 4; i0 += 128) {
        float4 xv[4], l[4];
        #pragma unroll
        for (int j = 0; j < 4; j++) { xv[j] = xp[i0 + 32 * j]; l[j] = le4[i0 + 32 * j]; }
        #pragma unroll
        for (int j = 0; j < 4; j++) {
            d += l[j].x * xv[j].x + l[j].y * xv[j].y + l[j].z * xv[j].z + l[j].w * xv[j].w;
            n += xv[j].x * xv[j].x + xv[j].y * xv[j].y + xv[j].z * xv[j].z + xv[j].w * xv[j].w;
            m += l[j].x * l[j].x + l[j].y * l[j].y + l[j].z * l[j].z + l[j].w * l[j].w;
        }
    }
    #pragma unroll
    for (int o = 16; o > 0; o >>= 1) {
        d += __shfl_xor_sync(0xffffffffu, d, o);
        n += __shfl_xor_sync(0xffffffffu, n, o);
        m += __shfl_xor_sync(0xffffffffu, m, o);
    }
    if (lane == 0) {
        float nle = fmaxf(sqrtf(m), EPSV);
        float nx = fmaxf(sqrtf(n), EPSV);
        g_interp[row] = d / (nle * nx);
    }
}

// ---------------------------------------------------------------------------
// K2: latch scan + fused pop partials. grid (KB2, B), block 128, float2/thread.
// ---------------------------------------------------------------------------
__global__ void k2_latch(const float* __restrict__ x, const float* __restrict__ latch0,
                         const float* __restrict__ sp, float* __restrict__ latches,
                         int T, int V) {
    __shared__ float s_i[256];
    __shared__ float s_wd[256][4];
    __shared__ float s_wn[256][4];
    __shared__ float s_sp[4];
    int b = blockIdx.y;
    int tid = threadIdx.x;
    int lane = tid & 31;
    int w = tid >> 5;
    int v2 = blockIdx.x * blockDim.x + tid;
    int stride2 = V >> 1;

    for (int t = tid; t < T; t += blockDim.x) s_i[t] = g_interp[b * T + t];
    __syncthreads();

    float2 sp2 = ((const float2*)sp)[v2];
    float2 latch = ((const float2*)(latch0 + (size_t)b * V))[v2];
    const float2* xp = (const float2*)(x + (size_t)b * T * V) + v2;
    float2* lp = (float2*)(latches + (size_t)b * T * V) + v2;

    {
        float d = sp2.x * latch.x + sp2.y * latch.y;
        float n = latch.x * latch.x + latch.y * latch.y;
        float m = sp2.x * sp2.x + sp2.y * sp2.y;
        #pragma unroll
        for (int o = 16; o > 0; o >>= 1) {
            d += __shfl_xor_sync(0xffffffffu, d, o);
            n += __shfl_xor_sync(0xffffffffu, n, o);
            m += __shfl_xor_sync(0xffffffffu, m, o);
        }
        if (lane == 0) { s_wd[0][w] = d; s_wn[0][w] = n; s_sp[w] = m; }
    }

    for (int t0 = 0; t0 < T; t0 += 8) {
        float2 xs[8];
        #pragma unroll
        for (int j = 0; j < 8; j++) xs[j] = xp[(size_t)(t0 + j) * stride2];
        float d8[8], n8[8];
        #pragma unroll
        for (int j = 0; j < 8; j++) {
            float i = s_i[t0 + j];
            latch.x = fmaf(i, xs[j].x - latch.x, latch.x);
            latch.y = fmaf(i, xs[j].y - latch.y, latch.y);
            lp[(size_t)(t0 + j) * stride2] = latch;
            d8[j] = sp2.x * latch.x + sp2.y * latch.y;
            n8[j] = latch.x * latch.x + latch.y * latch.y;
        }
        #pragma unroll
        for (int o = 16; o > 0; o >>= 1) {
            #pragma unroll
            for (int j = 0; j < 8; j++) {
                d8[j] += __shfl_xor_sync(0xffffffffu, d8[j], o);
                n8[j] += __shfl_xor_sync(0xffffffffu, n8[j], o);
            }
        }
        if (lane == 0) {
            #pragma unroll
            for (int j = 0; j < 8; j++) {
                int t = t0 + j;
                if (t + 1 < T) { s_wd[t + 1][w] = d8[j]; s_wn[t + 1][w] = n8[j]; }
            }
        }
    }
    __syncthreads();
    int pbase = (b * KB2 + blockIdx.x) * T;
    for (int t = tid; t < T; t += blockDim.x) {
        g_partd[pbase + t] = s_wd[t][0] + s_wd[t][1] + s_wd[t][2] + s_wd[t][3];
        g_partn[pbase + t] = s_wn[t][0] + s_wn[t][1] + s_wn[t][2] + s_wn[t][3];
    }
    if (b == 0 && tid == 0)
        g_partsp[blockIdx.x] = s_sp[0] + s_sp[1] + s_sp[2] + s_sp[3];
}

// ---------------------------------------------------------------------------
// K4: pops finalize + pointer scan (unnormalized chain, exact rho off-chain).
// ---------------------------------------------------------------------------
__global__ void k4_ptr(const float* __restrict__ sharp_ptr, float* __restrict__ pops, int T) {
    const unsigned FULL = 0xffffffffu;
    __shared__ float s_pop[256];
    int b = blockIdx.x;
    int lane = threadIdx.x;

    float sp2 = 0.f;
    #pragma unroll
    for (int blk = 0; blk < KB2; blk++) sp2 += g_partsp[blk];
    float nsp = fmaxf(sqrtf(sp2), EPSV);
    for (int t = lane; t < T; t += 32) {
        float d = 0.f, n = 0.f;
        #pragma unroll
        for (int blk = 0; blk < KB2; blk++) {
            d += g_partd[(b * KB2 + blk) * T + t];
            n += g_partn[(b * KB2 + blk) * T + t];
        }
        float nl = fmaxf(sqrtf(n), EPSV);
        float c = d / (nsp * nl);
        float p = (c > 0.0f) ? c : expm1f(c);
        s_pop[t] = p;
        pops[b * T + t] = p;
    }
    __syncwarp();

    bool active = lane < NSTACK;
    float sharp = sharp_ptr[0];
    bool fast5 = (sharp == 5.0f);
    float* cbase = g_coef + (size_t)b * T * CREC;
    int src_push = (lane + NSTACK - 1) % NSTACK;
    int src_pop = (lane + 1) % NSTACK;

    float u = (lane == 0) ? 1.0f : 0.0f;
    float rho = 1.0f;
    float lam = 1.0f, invlam = 1.0f;
    float Aacc = 1.0f;

    #pragma unroll 4
    for (int t = 0; t < T; t++) {
        float pop = s_pop[t];
        float push = 1.0f - pop;
        float pushs = push * lam;
        float popsc = pop * lam;
        float up = __shfl_sync(FULL, u, src_push);
        float upop = __shfl_sync(FULL, u, src_pop);
        float mh = fmaf(pushs, up, popsc * upop);
        float ph = active ? fmaxf(mh, 0.0f) : 0.0f;
        float u_next;
        if (fast5) {
            float p2 = ph * ph;
            u_next = (p2 * p2) * ph;
        } else {
            u_next = (ph > 0.f) ? powf(ph, sharp) : 0.f;
        }
        unsigned pb = __float_as_uint(ph);
        unsigned Mb;
        asm("redux.sync.max.u32 %0, %1, 0xffffffff;" : "=r"(Mb) : "r"(pb));
        int ep = (int)(Mb >> 23) - 127;
        int lexp = 127 - 5 * ep;
        lexp = lexp < 1 ? 1 : (lexp > 253 ? 253 : lexp);
        float lam_next = __uint_as_float((unsigned)lexp << 23);
        float invlam_next = __uint_as_float((unsigned)(254 - lexp) << 23);
        float S = u_next;
        #pragma unroll
        for (int o = 8; o > 0; o >>= 1) S += __shfl_xor_sync(FULL, S, o);
        float rg = rho * invlam;
        float kap;
        if (fast5) {
            float r2 = rg * rg;
            kap = (r2 * r2) * rg;
        } else {
            kap = powf(rg, sharp);
        }
        float rho_next = __fdividef(kap, fmaf(kap, S, EPSV));
        float vpush = rho * up;
        float vcur = rho * u;
        float a = push * (1.0f - vpush) + pop * (1.0f - vcur);
        float c = push * vpush;
        float q = rho_next * u_next;
        float* cf = cbase + (size_t)t * CREC;
        if (active) {
            cf[lane] = a;
            cf[12 + lane] = c;
            cf[24 + lane] = q;
        }
        if (lane == 0) {
            cf[36] = pop;
            cf[37] = rho_next * S;
        }
        Aacc *= a;
        if ((t & (CS - 1)) == CS - 1) {
            if (active) g_achunk[(b * NCH + (t >> 5)) * NSTACK + lane] = Aacc;
            Aacc = 1.0f;
        }
        u = u_next;
        rho = rho_next;
        lam = lam_next;
        invlam = invlam_next;
    }
}

// ---------------------------------------------------------------------------
// K6 (pass 1): replay chunk in y-space from y=0 -> W, packed f32x2 slot pairs.
// grid (4, NCH-1, B), block 256. W layout [b][ch][col][12].
// ---------------------------------------------------------------------------
__global__ void __launch_bounds__(256, 4)
k6_pass1(const float* __restrict__ x, int T, int V) {
    __shared__ __align__(16) float s_c[CS * CREC];
    int b = blockIdx.z, ch = blockIdx.y;
    int t0 = ch * CS;
    const float4* cg = (const float4*)(g_coef + ((size_t)b * T + t0) * CREC);
    float4* cs4 = (float4*)s_c;
    for (int i = threadIdx.x; i < CS * (CREC / 4); i += blockDim.x) cs4[i] = cg[i];
    __syncthreads();

    int colf2 = blockIdx.x * blockDim.x + threadIdx.x;  // float2 column 0..1023
    int s2 = V >> 1;
    const float2* xp = (const float2*)(x + (size_t)b * T * V) + (size_t)t0 * s2 + colf2;

    ull yx[6], yy[6];
    #pragma unroll
    for (int g = 0; g < 6; g++) { yx[g] = 0ull; yy[g] = 0ull; }

    float2 xbuf[4];
    #pragma unroll
    for (int j = 0; j < 4; j++) xbuf[j] = xp[(size_t)j * s2];

    for (int tt = 0; tt < CS; tt += 4) {
        #pragma unroll
        for (int j = 0; j < 4; j++) {
            int t = tt + j;
            float2 xv = xbuf[j];
            int tpre = (t + 4 < CS) ? t + 4 : CS - 1;
            xbuf[j] = xp[(size_t)tpre * s2];
            ull dupx = pack2(xv.x - ZEROOFF, xv.x - ZEROOFF);
            ull dupy = pack2(xv.y - ZEROOFF, xv.y - ZEROOFF);
            const ulonglong2* ap = (const ulonglong2*)(s_c + t * CREC);
            const ulonglong2* cp = (const ulonglong2*)(s_c + t * CREC + 12);
            #pragma unroll
            for (int h = 0; h < 3; h++) {
                ulonglong2 a2 = ap[h];
                ulonglong2 c2 = cp[h];
                yx[2 * h]     = fma2(a2.x, yx[2 * h],     mul2(c2.x, dupx));
                yx[2 * h + 1] = fma2(a2.y, yx[2 * h + 1], mul2(c2.y, dupx));
                yy[2 * h]     = fma2(a2.x, yy[2 * h],     mul2(c2.x, dupy));
                yy[2 * h + 1] = fma2(a2.y, yy[2 * h + 1], mul2(c2.y, dupy));
            }
        }
    }
    // store W: [b][ch][col][12], 3 STG.128 per element
    int col0 = colf2 * 2;
    ulonglong2* Wx = (ulonglong2*)(g_W + (((size_t)(b * NCH + ch)) * 2048 + col0) * NSTACK);
    ulonglong2* Wy = (ulonglong2*)(g_W + (((size_t)(b * NCH + ch)) * 2048 + col0 + 1) * NSTACK);
    #pragma unroll
    for (int h = 0; h < 3; h++) {
        ulonglong2 wx2; wx2.x = yx[2 * h]; wx2.y = yx[2 * h + 1];
        ulonglong2 wy2; wy2.x = yy[2 * h]; wy2.y = yy[2 * h + 1];
        Wx[h] = wx2;
        Wy[h] = wy2;
    }
}

// ---------------------------------------------------------------------------
// K8 (pass 2, fused combine): packed start-state fold + packed replay.
// grid (4, NCH, B), block 256.
// ---------------------------------------------------------------------------
__global__ void __launch_bounds__(256, 4)
k8_pass2(const float* __restrict__ x, float* __restrict__ outs,
         float* __restrict__ tops, int T, int V) {
    __shared__ __align__(16) float s_c[CS * CREC];
    __shared__ __align__(16) float sA[NCH - 1][NSTACK];
    int b = blockIdx.z, ch = blockIdx.y;
    int t0 = ch * CS;
    const float4* cg = (const float4*)(g_coef + ((size_t)b * T + t0) * CREC);
    float4* cs4 = (float4*)s_c;
    for (int i = threadIdx.x; i < CS * (CREC / 4); i += blockDim.x) cs4[i] = cg[i];
    if (threadIdx.x < (NCH - 1) * NSTACK)
        sA[threadIdx.x / NSTACK][threadIdx.x % NSTACK] =
            g_achunk[b * NCH * NSTACK + threadIdx.x];
    __syncthreads();

    int colf2 = blockIdx.x * blockDim.x + threadIdx.x;
    int s2 = V >> 1;
    const float2* xp = (const float2*)(x + (size_t)b * T * V) + (size_t)t0 * s2 + colf2;
    float2* op = (float2*)(outs + (size_t)b * T * V) + (size_t)t0 * s2 + colf2;
    float2* tp = (float2*)(tops + (size_t)b * T * V) + (size_t)t0 * s2 + colf2;

    ull yx[6], yy[6];
    #pragma unroll
    for (int g = 0; g < 6; g++) { yx[g] = 0ull; yy[g] = 0ull; }

    int col0 = colf2 * 2;
    for (int j = 0; j < ch; j++) {
        const ulonglong2* Wx = (const ulonglong2*)(g_W + (((size_t)(b * NCH + j)) * 2048 + col0) * NSTACK);
        const ulonglong2* Wy = (const ulonglong2*)(g_W + (((size_t)(b * NCH + j)) * 2048 + col0 + 1) * NSTACK);
        const ulonglong2* Ap = (const ulonglong2*)&sA[j][0];
        #pragma unroll
        for (int h = 0; h < 3; h++) {
            ulonglong2 a2 = Ap[h];
            ulonglong2 wx2 = Wx[h];
            ulonglong2 wy2 = Wy[h];
            yx[2 * h]     = fma2(a2.x, yx[2 * h],     wx2.x);
            yx[2 * h + 1] = fma2(a2.y, yx[2 * h + 1], wx2.y);
            yy[2 * h]     = fma2(a2.x, yy[2 * h],     wy2.x);
            yy[2 * h + 1] = fma2(a2.y, yy[2 * h + 1], wy2.y);
        }
    }

    float2 xbuf[4];
    #pragma unroll
    for (int j = 0; j < 4; j++) xbuf[j] = xp[(size_t)j * s2];

    for (int tt = 0; tt < CS; tt += 4) {
        #pragma unroll
        for (int j = 0; j < 4; j++) {
            int t = tt + j;
            float2 xv = xbuf[j];
            int tpre = (t + 4 < CS) ? t + 4 : CS - 1;
            xbuf[j] = xp[(size_t)tpre * s2];
            ull dupx = pack2(xv.x - ZEROOFF, xv.x - ZEROOFF);
            ull dupy = pack2(xv.y - ZEROOFF, xv.y - ZEROOFF);
            const ulonglong2* ap = (const ulonglong2*)(s_c + t * CREC);
            const ulonglong2* cp = (const ulonglong2*)(s_c + t * CREC + 12);
            const ulonglong2* qp = (const ulonglong2*)(s_c + t * CREC + 24);
            ull taccx = 0ull, taccy = 0ull;
            #pragma unroll
            for (int h = 0; h < 3; h++) {
                ulonglong2 a2 = ap[h];
                ulonglong2 c2 = cp[h];
                ulonglong2 q2 = qp[h];
                yx[2 * h]     = fma2(a2.x, yx[2 * h],     mul2(c2.x, dupx));
                yx[2 * h + 1] = fma2(a2.y, yx[2 * h + 1], mul2(c2.y, dupx));
                yy[2 * h]     = fma2(a2.x, yy[2 * h],     mul2(c2.x, dupy));
                yy[2 * h + 1] = fma2(a2.y, yy[2 * h + 1], mul2(c2.y, dupy));
                taccx = fma2(yx[2 * h], q2.x, taccx);
                taccx = fma2(yx[2 * h + 1], q2.y, taccx);
                taccy = fma2(yy[2 * h], q2.x, taccy);
                taccy = fma2(yy[2 * h + 1], q2.y, taccy);
            }
            float tlx, thx, tly, thy;
            unpack2(taccx, tlx, thx);
            unpack2(taccy, tly, thy);
            float2 meta = *(const float2*)(s_c + t * CREC + 36);  // pop, sq
            float topx = fmaf(ZEROOFF, meta.y, tlx + thx);
            float topy = fmaf(ZEROOFF, meta.y, tly + thy);
            float2 o2; o2.x = meta.x * topx; o2.y = meta.x * topy;
            float2 t2; t2.x = topx; t2.y = topy;
            op[(size_t)t * s2] = o2;
            tp[(size_t)t * s2] = t2;
        }
    }
}

// ---------------------------------------------------------------------------
// Launch (6 kernels incl. splitter). Output: [outs][latches][pops][tops]
// ---------------------------------------------------------------------------
extern "C" void kernel_launch(void* const* d_in, const int* in_sizes, int n_in,
                              void* d_out, int out_size) {
    const float* x = (const float*)d_in[0];
    const float* sp = (const float*)d_in[1];
    const float* shp = (const float*)d_in[2];
    const float* le = (const float*)d_in[3];
    const float* l0 = (const float*)d_in[4];

    int V = in_sizes[1];
    int B = in_sizes[4] / V;
    int T = in_sizes[0] / in_sizes[4];

    float* out = (float*)d_out;
    size_t btv = (size_t)B * T * V;
    float* outs = out;
    float* latches = out + btv;
    float* pops = out + 2 * btv;
    float* tops = out + 2 * btv + (size_t)B * T;

    kz_split<<<1, 32>>>();
    k1_interp<<<B * T / 8, 256>>>(x, le, V);
    dim3 g2(KB2, B);
    k2_latch<<<g2, 128>>>(x, l0, sp, latches, T, V);
    k4_ptr<<<B, 32>>>(shp, pops, T);
    dim3 g6(V / 512, NCH - 1, B);
    k6_pass1<<<g6, 256>>>(x, T, V);
    dim3 g8(V / 512, NCH, B);
    k8_pass2<<<g8, 256>>>(x, outs, tops, T, V);
}